// round 16
// baseline (speedup 1.0000x reference)
#include <cuda_runtime.h>
#include <cuda_fp16.h>
#include <cstdint>

#define NE 16
#define NT 2048
#define NH 1024
#define NI 768

// ---------------- scratch (static, no runtime allocation) ----------------
__device__ int   g_cnt[NE];
__device__ int   g_tok[NE][NT];
__device__ float g_wt[NE][NT];
__device__ int   g_done[NE];    // gateup tile completion (thread-granular)
__device__ __align__(16) __half g_x16[(size_t)NT * NH];
__device__ __align__(16) __half g_wg16[(size_t)NE * NI * NH];
__device__ __align__(16) __half g_wu16[(size_t)NE * NI * NH];
__device__ __align__(16) __half g_wd16[(size_t)NE * NH * NI];
__device__ __align__(16) __half g_hmid16[(size_t)NE * NT * NI];

// ---------------- PTX helpers ----------------
__device__ __forceinline__ uint32_t smem_u32(const void* p) {
    uint32_t a;
    asm("{ .reg .u64 t; cvta.to.shared.u64 t, %1; cvt.u32.u64 %0, t; }" : "=r"(a) : "l"(p));
    return a;
}
__device__ __forceinline__ uint32_t packf16(float lo, float hi) {
    uint32_t r;
    asm("cvt.rn.f16x2.f32 %0, %1, %2;" : "=r"(r) : "f"(hi), "f"(lo));
    return r;
}
__device__ __forceinline__ int ld_acq(const int* p) {
    int v;
    asm volatile("ld.acquire.gpu.global.s32 %0, [%1];" : "=r"(v) : "l"(p) : "memory");
    return v;
}
__device__ __forceinline__ void cp16(uint32_t dst, const void* src, bool valid) {
    if (valid)
        asm volatile("cp.async.cg.shared.global [%0], [%1], 16;" :: "r"(dst), "l"(src) : "memory");
    else
        asm volatile("cp.async.cg.shared.global [%0], [%1], 16, 0;" :: "r"(dst), "l"(src) : "memory");
}
#define CP_COMMIT() asm volatile("cp.async.commit_group;" ::: "memory")
#define CP_WAIT1()  asm volatile("cp.async.wait_group 1;" ::: "memory")
#define CP_WAIT0()  asm volatile("cp.async.wait_group 0;" ::: "memory")

#define LDSM4(R, addr)                                                                 \
    asm volatile("ldmatrix.sync.aligned.m8n8.x4.shared.b16 {%0,%1,%2,%3}, [%4];"       \
                 : "=r"((R)[0]), "=r"((R)[1]), "=r"((R)[2]), "=r"((R)[3]) : "r"(addr))

__device__ __forceinline__ void mma16(float* d, const uint32_t* a, uint32_t b0, uint32_t b1) {
    asm volatile(
        "mma.sync.aligned.m16n8k16.row.col.f32.f16.f16.f32 "
        "{%0,%1,%2,%3},{%4,%5,%6,%7},{%8,%9},{%0,%1,%2,%3};"
        : "+f"(d[0]), "+f"(d[1]), "+f"(d[2]), "+f"(d[3])
        : "r"(a[0]), "r"(a[1]), "r"(a[2]), "r"(a[3]), "r"(b0), "r"(b1));
}

// ---------------- kernel 1: router + zero(out) + cvt(gate,up,x) ----------------
#define PRE_RBLK 256
#define PRE_CBLK 2048
#define PRE_SMEM (8 * NH * 4)   // 32KB

__global__ void __launch_bounds__(256) k_pre(const float* __restrict__ x,
                                             const float* __restrict__ gw,
                                             const float* __restrict__ gp,
                                             const float* __restrict__ up,
                                             float* __restrict__ out) {
    if (blockIdx.x < PRE_RBLK) {
        // ---------------- router (gate_w staged 8 experts per pass) ----------------
        extern __shared__ unsigned char s_raw[];
        float* sgw = (float*)s_raw;

        int lane = threadIdx.x & 31;
        int tok  = (blockIdx.x * 256 + threadIdx.x) >> 5;
        const float* xr = x + (size_t)tok * NH;

        float xs[32];
#pragma unroll
        for (int j = 0; j < 32; j++) xs[j] = xr[lane + j * 32];

        float lg[NE];
#pragma unroll
        for (int half = 0; half < 2; half++) {
            __syncthreads();
            for (int i = threadIdx.x; i < 8 * NH / 4; i += 256)
                ((float4*)sgw)[i] = ((const float4*)(gw + half * 8 * NH))[i];
            __syncthreads();
#pragma unroll
            for (int ee = 0; ee < 8; ee++) {
                const float* wr = sgw + ee * NH;
                float p = 0.f;
#pragma unroll
                for (int j = 0; j < 32; j++) p += xs[j] * wr[lane + j * 32];
#pragma unroll
                for (int o = 16; o > 0; o >>= 1) p += __shfl_xor_sync(0xffffffffu, p, o);
                lg[half * 8 + ee] = p;
            }
        }

        if (lane == 0) {
            int i1 = 0; float v1 = lg[0];
#pragma unroll
            for (int e = 1; e < NE; e++) if (lg[e] > v1) { v1 = lg[e]; i1 = e; }
            int i2 = -1; float v2 = -1e30f;
#pragma unroll
            for (int e = 0; e < NE; e++) if (e != i1 && lg[e] > v2) { v2 = lg[e]; i2 = e; }
            float e2 = expf(v2 - v1);
            float s  = 1.f + e2;
            int p1 = atomicAdd(&g_cnt[i1], 1);
            g_tok[i1][p1] = tok; g_wt[i1][p1] = 1.f / s;
            int p2 = atomicAdd(&g_cnt[i2], 1);
            g_tok[i2][p2] = tok; g_wt[i2][p2] = e2 / s;
        }
    } else {
        // ---------------- zero(out) + cvt(gate, up, x) ----------------
        const size_t W8 = (size_t)NE * NI * NH / 8;
        const size_t X8 = (size_t)NT * NH / 8;
        const size_t Z8 = (size_t)NT * NH / 8;
        const size_t tot = 2 * W8 + X8 + Z8;
        for (size_t i = (size_t)(blockIdx.x - PRE_RBLK) * blockDim.x + threadIdx.x; i < tot;
             i += (size_t)PRE_CBLK * blockDim.x) {
            if (i >= 2 * W8 + X8) {
                size_t j = i - (2 * W8 + X8);
                float4 z = make_float4(0.f, 0.f, 0.f, 0.f);
                ((float4*)out)[2 * j]     = z;
                ((float4*)out)[2 * j + 1] = z;
                continue;
            }
            const float* src; __half* dst; size_t j;
            if (i < W8)            { src = gp; dst = g_wg16; j = i; }
            else if (i < 2 * W8)   { src = up; dst = g_wu16; j = i - W8; }
            else                   { src = x;  dst = g_x16;  j = i - 2 * W8; }
            float4 f0 = ((const float4*)src)[2 * j];
            float4 f1 = ((const float4*)src)[2 * j + 1];
            uint4 o;
            o.x = packf16(f0.x, f0.y);
            o.y = packf16(f0.z, f0.w);
            o.z = packf16(f1.x, f1.y);
            o.w = packf16(f1.z, f1.w);
            ((uint4*)dst)[j] = o;
        }
    }
}

// ---------------- kernel 2: fused MoE (gateup z<NE | down z>=NE) ----------------
// z in [0,NE):   gateup GEMM+SwiGLU for expert z; releases g_done[z] per thread.
// z in [NE,2NE): down GEMM for expert z-NE. Prologue: this CTA converts ITS OWN
//                down_proj B tile fp32->fp16 (benign duplicate writes across
//                m-tiles), then gates on g_done[e], then standard pipeline.
#define MOE_SMEM (3 * 32768)

__global__ void __launch_bounds__(256, 2) k_moe(const float* __restrict__ dp,
                                                float* __restrict__ out) {
    int t = threadIdx.x, wid = t >> 5, lane = t & 31;
    extern __shared__ unsigned char s_raw[];
    uint32_t sb = smem_u32(s_raw);

    if (blockIdx.z < NE) {
        // =================== gateup GEMM + SwiGLU ===================
        int e   = blockIdx.z;
        int cnt = g_cnt[e];
        int m0  = blockIdx.y * 128;
        if (m0 >= cnt) return;
        int n0  = blockIdx.x * 64;

        int arow = t & 127, ac0 = (t >> 7) * 4;
        int tokA = (m0 + arow < cnt) ? g_tok[e][m0 + arow] : -1;
        const __half* aSrc = g_x16 + (size_t)(tokA < 0 ? 0 : tokA) * NH;
        uint32_t aDst = arow * 128;
        int aS = arow & 7;

        int grow = t & 63, gc0 = (t >> 6) * 2;
        const __half* gSrc = g_wg16 + ((size_t)e * NI + n0 + grow) * NH;
        const __half* uSrc = g_wu16 + ((size_t)e * NI + n0 + grow) * NH;
        uint32_t gDst = grow * 128;
        int gS = grow & 7;

        auto stage = [&](int kt, int st) {
            uint32_t base = sb + st * 32768;
#pragma unroll
            for (int j = 0; j < 4; j++) {
                int c = ac0 + j;
                cp16(base + aDst + ((c ^ aS) << 4), aSrc + kt * 64 + c * 8, tokA >= 0);
            }
#pragma unroll
            for (int j = 0; j < 2; j++) {
                int c = gc0 + j;
                cp16(base + 16384 + gDst + ((c ^ gS) << 4), gSrc + kt * 64 + c * 8, true);
                cp16(base + 24576 + gDst + ((c ^ gS) << 4), uSrc + kt * 64 + c * 8, true);
            }
            CP_COMMIT();
        };

        int wm = (wid & 3) * 32;
        int wn = (wid >> 2) * 32;
        int s7 = lane & 7;
        uint32_t aLdBase = sb + (wm + (lane & 7) + 8 * ((lane >> 3) & 1)) * 128;
        int aHi = lane >> 4;
        uint32_t bRow = (lane & 7) + 8 * (lane >> 4);
        int bHi = (lane >> 3) & 1;
        uint32_t gLdBase = sb + 16384 + (wn + bRow) * 128;
        uint32_t uLdBase = sb + 24576 + (wn + bRow) * 128;

        float accG[2][4][4] = {}, accU[2][4][4] = {};

        auto compute = [&](int st) {
            uint32_t so = st * 32768;
#pragma unroll
            for (int kf = 0; kf < 4; kf++) {
                uint32_t a[2][4], g[2][4], u[2][4];
                uint32_t aoff = (((2 * kf + aHi) ^ s7) << 4);
                uint32_t boff = (((2 * kf + bHi) ^ s7) << 4);
#pragma unroll
                for (int mf = 0; mf < 2; mf++) LDSM4(a[mf], aLdBase + so + mf * 2048 + aoff);
#pragma unroll
                for (int p = 0; p < 2; p++) {
                    LDSM4(g[p], gLdBase + so + p * 2048 + boff);
                    LDSM4(u[p], uLdBase + so + p * 2048 + boff);
                }
#pragma unroll
                for (int mf = 0; mf < 2; mf++)
#pragma unroll
                    for (int nf = 0; nf < 4; nf++) {
                        int p = nf >> 1, o = (nf & 1) * 2;
                        mma16(accG[mf][nf], a[mf], g[p][o], g[p][o + 1]);
                        mma16(accU[mf][nf], a[mf], u[p][o], u[p][o + 1]);
                    }
            }
        };

        const int NK = NH / 64;   // 16
        stage(0, 0);
        stage(1, 1);
        int st = 0;
        for (int kt = 0; kt < NK; kt++) {
            if (kt == NK - 1) { CP_WAIT0(); } else { CP_WAIT1(); }
            __syncthreads();
            compute(st);
            if (kt + 2 < NK) stage(kt + 2, (st + 2) % 3);
            st = (st + 1) % 3;
        }

        int tg = lane >> 2, tc = lane & 3;
#pragma unroll
        for (int mf = 0; mf < 2; mf++) {
            int s0 = m0 + wm + mf * 16 + tg;
            int s1 = s0 + 8;
#pragma unroll
            for (int nf = 0; nf < 4; nf++) {
                int c = n0 + wn + nf * 8 + 2 * tc;
                const float* dG = accG[mf][nf];
                const float* dU = accU[mf][nf];
                if (s0 < cnt) {
                    float h0 = (dG[0] / (1.f + __expf(-dG[0]))) * dU[0];
                    float h1 = (dG[1] / (1.f + __expf(-dG[1]))) * dU[1];
                    *(uint32_t*)(g_hmid16 + ((size_t)e * NT + s0) * NI + c) = packf16(h0, h1);
                }
                if (s1 < cnt) {
                    float h2 = (dG[2] / (1.f + __expf(-dG[2]))) * dU[2];
                    float h3 = (dG[3] / (1.f + __expf(-dG[3]))) * dU[3];
                    *(uint32_t*)(g_hmid16 + ((size_t)e * NT + s1) * NI + c) = packf16(h2, h3);
                }
            }
        }
        __threadfence();
        atomicAdd(&g_done[e], 1);    // per-thread release
        return;
    }

    // =================== down GEMM + weighted combine ===================
    if (blockIdx.x >= NH / 128) return;
    int e   = blockIdx.z - NE;
    int cnt = g_cnt[e];
    int m0  = blockIdx.y * 128;
    if (m0 >= cnt) return;
    int n0  = blockIdx.x * 128;

    // ---- prologue: convert THIS CTA's down_proj B tile fp32 -> fp16 ----
    // Tile = dp rows [e*NH + n0, +128), all NI cols. Duplicate conversion across
    // m-tile CTAs writes identical bytes (benign race).
    {
        const float4* src = (const float4*)(dp + ((size_t)e * NH + n0) * NI);
        uint4* dst = (uint4*)(g_wd16 + ((size_t)e * NH + n0) * NI);
        const int n8 = 128 * NI / 8;   // 12288 8-elem chunks
        for (int i = t; i < n8; i += 256) {
            float4 f0 = src[2 * i];
            float4 f1 = src[2 * i + 1];
            uint4 o;
            o.x = packf16(f0.x, f0.y);
            o.y = packf16(f0.z, f0.w);
            o.z = packf16(f1.x, f1.y);
            o.w = packf16(f1.z, f1.w);
            dst[i] = o;
        }
        __threadfence();
    }

    // gate on this expert's gateup tiles (spin absorbs residual gateup time)
    int need = ((cnt + 127) >> 7) * (NI / 64) * 256;
    if (t == 0) {
        while (ld_acq(&g_done[e]) < need) __nanosleep(256);
    }
    __syncthreads();

    int arow = t & 127, ac0 = (t >> 7) * 4;
    bool aValid = (m0 + arow < cnt);
    const __half* aSrc = g_hmid16 + ((size_t)e * NT + (aValid ? m0 + arow : 0)) * NI;
    uint32_t aDst = arow * 128;
    int aS = arow & 7;

    int brow = t & 127, bc0 = (t >> 7) * 4;
    const __half* bSrc = g_wd16 + ((size_t)e * NH + n0 + brow) * NI;
    uint32_t bDstO = 16384 + brow * 128;
    int bS = brow & 7;

    auto stage = [&](int kt, int st) {
        uint32_t base = sb + st * 32768;
#pragma unroll
        for (int j = 0; j < 4; j++) {
            int c = ac0 + j;
            cp16(base + aDst + ((c ^ aS) << 4), aSrc + kt * 64 + c * 8, aValid);
            int cb = bc0 + j;
            cp16(base + bDstO + ((cb ^ bS) << 4), bSrc + kt * 64 + cb * 8, true);
        }
        CP_COMMIT();
    };

    int wm = (wid & 3) * 32;
    int wn = (wid >> 2) * 64;
    int s7 = lane & 7;
    uint32_t aLdBase = sb + (wm + (lane & 7) + 8 * ((lane >> 3) & 1)) * 128;
    int aHi = lane >> 4;
    uint32_t bRow = (lane & 7) + 8 * (lane >> 4);
    int bHi = (lane >> 3) & 1;
    uint32_t bLdBase = sb + 16384 + (wn + bRow) * 128;

    float acc[2][8][4] = {};

    auto compute = [&](int st) {
        uint32_t so = st * 32768;
#pragma unroll
        for (int kf = 0; kf < 4; kf++) {
            uint32_t a[2][4], b[4][4];
            uint32_t aoff = (((2 * kf + aHi) ^ s7) << 4);
            uint32_t boff = (((2 * kf + bHi) ^ s7) << 4);
#pragma unroll
            for (int mf = 0; mf < 2; mf++) LDSM4(a[mf], aLdBase + so + mf * 2048 + aoff);
#pragma unroll
            for (int p = 0; p < 4; p++) LDSM4(b[p], bLdBase + so + p * 2048 + boff);
#pragma unroll
            for (int mf = 0; mf < 2; mf++)
#pragma unroll
                for (int nf = 0; nf < 8; nf++) {
                    int p = nf >> 1, o = (nf & 1) * 2;
                    mma16(acc[mf][nf], a[mf], b[p][o], b[p][o + 1]);
                }
        }
    };

    const int NK = NI / 64;   // 12
    stage(0, 0);
    stage(1, 1);
    int st = 0;
    for (int kt = 0; kt < NK; kt++) {
        if (kt == NK - 1) { CP_WAIT0(); } else { CP_WAIT1(); }
        __syncthreads();
        compute(st);
        if (kt + 2 < NK) stage(kt + 2, (st + 2) % 3);
        st = (st + 1) % 3;
    }

    int tg = lane >> 2, tc = lane & 3;
#pragma unroll
    for (int mf = 0; mf < 2; mf++) {
        int s0 = m0 + wm + mf * 16 + tg;
        int s1 = s0 + 8;
        int tok0 = -1, tok1 = -1; float w0 = 0.f, w1 = 0.f;
        if (s0 < cnt) { tok0 = g_tok[e][s0]; w0 = g_wt[e][s0]; }
        if (s1 < cnt) { tok1 = g_tok[e][s1]; w1 = g_wt[e][s1]; }
#pragma unroll
        for (int nf = 0; nf < 8; nf++) {
            int c = n0 + wn + nf * 8 + 2 * tc;
            const float* d = acc[mf][nf];
            if (tok0 >= 0) {
                atomicAdd(out + (size_t)tok0 * NH + c,     w0 * d[0]);
                atomicAdd(out + (size_t)tok0 * NH + c + 1, w0 * d[1]);
            }
            if (tok1 >= 0) {
                atomicAdd(out + (size_t)tok1 * NH + c,     w1 * d[2]);
                atomicAdd(out + (size_t)tok1 * NH + c + 1, w1 * d[3]);
            }
        }
    }
}

// ---------------- launch ----------------
extern "C" void kernel_launch(void* const* d_in, const int* in_sizes, int n_in,
                              void* d_out, int out_size) {
    (void)in_sizes; (void)n_in; (void)out_size;
    const float* x  = (const float*)d_in[0];
    const float* gw = (const float*)d_in[1];
    const float* gp = (const float*)d_in[2];
    const float* up = (const float*)d_in[3];
    const float* dp = (const float*)d_in[4];
    float* out = (float*)d_out;

    cudaFuncSetAttribute(k_moe, cudaFuncAttributeMaxDynamicSharedMemorySize, MOE_SMEM);

    void* p0 = nullptr; void* p1 = nullptr;
    cudaGetSymbolAddress(&p0, g_cnt);
    cudaGetSymbolAddress(&p1, g_done);
    cudaMemsetAsync(p0, 0, NE * sizeof(int));
    cudaMemsetAsync(p1, 0, NE * sizeof(int));

    k_pre<<<PRE_RBLK + PRE_CBLK, 256, PRE_SMEM>>>(x, gw, gp, up, out);
    k_moe<<<dim3(NI / 64, 16, 2 * NE), 256, MOE_SMEM>>>(dp, out);
}

// round 17
// speedup vs baseline: 1.1045x; 1.1045x over previous
#include <cuda_runtime.h>
#include <cuda_fp16.h>
#include <cstdint>

#define NE 16
#define NT 2048
#define NH 1024
#define NI 768

// ---------------- scratch (static, no runtime allocation) ----------------
__device__ int   g_cnt[NE];
__device__ int   g_tok[NE][NT];
__device__ float g_wt[NE][NT];
__device__ __align__(16) __half g_x16[(size_t)NT * NH];
__device__ __align__(16) __half g_wg16[(size_t)NE * NI * NH];
__device__ __align__(16) __half g_wu16[(size_t)NE * NI * NH];
__device__ __align__(16) __half g_wd16[(size_t)NE * NH * NI];
__device__ __align__(16) __half g_hmid16[(size_t)NE * NT * NI];

// ---------------- PTX helpers ----------------
__device__ __forceinline__ uint32_t smem_u32(const void* p) {
    uint32_t a;
    asm("{ .reg .u64 t; cvta.to.shared.u64 t, %1; cvt.u32.u64 %0, t; }" : "=r"(a) : "l"(p));
    return a;
}
__device__ __forceinline__ uint32_t packf16(float lo, float hi) {
    uint32_t r;
    asm("cvt.rn.f16x2.f32 %0, %1, %2;" : "=r"(r) : "f"(hi), "f"(lo));
    return r;
}
__device__ __forceinline__ void cp16(uint32_t dst, const void* src, bool valid) {
    if (valid)
        asm volatile("cp.async.cg.shared.global [%0], [%1], 16;" :: "r"(dst), "l"(src) : "memory");
    else
        asm volatile("cp.async.cg.shared.global [%0], [%1], 16, 0;" :: "r"(dst), "l"(src) : "memory");
}
#define CP_COMMIT() asm volatile("cp.async.commit_group;" ::: "memory")
#define CP_WAIT1()  asm volatile("cp.async.wait_group 1;" ::: "memory")
#define CP_WAIT0()  asm volatile("cp.async.wait_group 0;" ::: "memory")

#define LDSM4(R, addr)                                                                 \
    asm volatile("ldmatrix.sync.aligned.m8n8.x4.shared.b16 {%0,%1,%2,%3}, [%4];"       \
                 : "=r"((R)[0]), "=r"((R)[1]), "=r"((R)[2]), "=r"((R)[3]) : "r"(addr))

__device__ __forceinline__ void mma16(float* d, const uint32_t* a, uint32_t b0, uint32_t b1) {
    asm volatile(
        "mma.sync.aligned.m16n8k16.row.col.f32.f16.f16.f32 "
        "{%0,%1,%2,%3},{%4,%5,%6,%7},{%8,%9},{%0,%1,%2,%3};"
        : "+f"(d[0]), "+f"(d[1]), "+f"(d[2]), "+f"(d[3])
        : "r"(a[0]), "r"(a[1]), "r"(a[2]), "r"(a[3]), "r"(b0), "r"(b1));
}

// ---------------- kernel 1: fused router + cvt(gate,up,x) ----------------
// Router stages gate_w in FOUR 16KB passes so launch-wide smem reservation is
// 16KB -> cvt blocks reach the 8 CTA/SM thread limit.
#define PRE_RBLK 256
#define PRE_CBLK 2048
#define PRE_SMEM (4 * NH * 4)   // 16KB

__global__ void __launch_bounds__(256) k_pre(const float* __restrict__ x,
                                             const float* __restrict__ gw,
                                             const float* __restrict__ gp,
                                             const float* __restrict__ up) {
    if (blockIdx.x < PRE_RBLK) {
        // ---------------- router (gate_w staged 4 experts per pass) ----------------
        extern __shared__ unsigned char s_raw[];
        float* sgw = (float*)s_raw;   // [4 * NH]

        int lane = threadIdx.x & 31;
        int tok  = (blockIdx.x * 256 + threadIdx.x) >> 5;
        const float* xr = x + (size_t)tok * NH;

        float xs[32];
#pragma unroll
        for (int j = 0; j < 32; j++) xs[j] = xr[lane + j * 32];

        float lg[NE];
#pragma unroll
        for (int q = 0; q < 4; q++) {
            __syncthreads();
            for (int i = threadIdx.x; i < 4 * NH / 4; i += 256)
                ((float4*)sgw)[i] = ((const float4*)(gw + q * 4 * NH))[i];
            __syncthreads();
#pragma unroll
            for (int ee = 0; ee < 4; ee++) {
                const float* wr = sgw + ee * NH;
                float p = 0.f;
#pragma unroll
                for (int j = 0; j < 32; j++) p += xs[j] * wr[lane + j * 32];
#pragma unroll
                for (int o = 16; o > 0; o >>= 1) p += __shfl_xor_sync(0xffffffffu, p, o);
                lg[q * 4 + ee] = p;
            }
        }

        if (lane == 0) {
            int i1 = 0; float v1 = lg[0];
#pragma unroll
            for (int e = 1; e < NE; e++) if (lg[e] > v1) { v1 = lg[e]; i1 = e; }
            int i2 = -1; float v2 = -1e30f;
#pragma unroll
            for (int e = 0; e < NE; e++) if (e != i1 && lg[e] > v2) { v2 = lg[e]; i2 = e; }
            float e2 = expf(v2 - v1);
            float s  = 1.f + e2;
            int p1 = atomicAdd(&g_cnt[i1], 1);
            g_tok[i1][p1] = tok; g_wt[i1][p1] = 1.f / s;
            int p2 = atomicAdd(&g_cnt[i2], 1);
            g_tok[i2][p2] = tok; g_wt[i2][p2] = e2 / s;
        }
    } else {
        // ---------------- cvt(gate, up, x) ----------------
        const size_t W8 = (size_t)NE * NI * NH / 8;
        const size_t X8 = (size_t)NT * NH / 8;
        const size_t tot = 2 * W8 + X8;
        for (size_t i = (size_t)(blockIdx.x - PRE_RBLK) * blockDim.x + threadIdx.x; i < tot;
             i += (size_t)PRE_CBLK * blockDim.x) {
            const float* src; __half* dst; size_t j;
            if (i < W8)            { src = gp; dst = g_wg16; j = i; }
            else if (i < 2 * W8)   { src = up; dst = g_wu16; j = i - W8; }
            else                   { src = x;  dst = g_x16;  j = i - 2 * W8; }
            float4 f0 = ((const float4*)src)[2 * j];
            float4 f1 = ((const float4*)src)[2 * j + 1];
            uint4 o;
            o.x = packf16(f0.x, f0.y);
            o.y = packf16(f0.z, f0.w);
            o.z = packf16(f1.x, f1.y);
            o.w = packf16(f1.z, f1.w);
            ((uint4*)dst)[j] = o;
        }
    }
}

// ---------------- kernel 2: fused gate/up GEMM + SwiGLU -> g_hmid16 ----------------
// z < NE: GEMM CTAs (M=128, N=64, K=64/stage, 3x32KB stages, single barrier/iter).
// z == NE: 192 DRAM-bound CTAs: down_proj cvt + out-zeroing (hidden under GEMM).
#define GU_SMEM (3 * 32768)

__global__ void __launch_bounds__(256, 2) k_gateup(const float* __restrict__ dp,
                                                   float* __restrict__ out) {
    if (blockIdx.z == NE) {
        // ---- down_proj cvt + zero(out), hidden under the GEMM ----
        const size_t W8 = (size_t)NE * NH * NI / 8;
        const size_t Z8 = (size_t)NT * NH / 8;
        size_t nb   = (size_t)gridDim.x * gridDim.y;
        size_t bid  = (size_t)blockIdx.y * gridDim.x + blockIdx.x;
        for (size_t i = bid * blockDim.x + threadIdx.x; i < W8 + Z8; i += nb * blockDim.x) {
            if (i >= W8) {
                size_t j = i - W8;
                float4 z = make_float4(0.f, 0.f, 0.f, 0.f);
                ((float4*)out)[2 * j]     = z;
                ((float4*)out)[2 * j + 1] = z;
                continue;
            }
            float4 f0 = ((const float4*)dp)[2 * i];
            float4 f1 = ((const float4*)dp)[2 * i + 1];
            uint4 o;
            o.x = packf16(f0.x, f0.y);
            o.y = packf16(f0.z, f0.w);
            o.z = packf16(f1.x, f1.y);
            o.w = packf16(f1.z, f1.w);
            ((uint4*)g_wd16)[i] = o;
        }
        return;
    }

    int e   = blockIdx.z;
    int cnt = g_cnt[e];
    int m0  = blockIdx.y * 128;
    if (m0 >= cnt) return;
    int n0  = blockIdx.x * 64;

    extern __shared__ unsigned char s_raw[];
    uint32_t sb = smem_u32(s_raw);

    int t = threadIdx.x, wid = t >> 5, lane = t & 31;

    // ---- staging setup ----
    int arow = t & 127, ac0 = (t >> 7) * 4;
    int tokA = (m0 + arow < cnt) ? g_tok[e][m0 + arow] : -1;
    const __half* aSrc = g_x16 + (size_t)(tokA < 0 ? 0 : tokA) * NH;
    uint32_t aDst = arow * 128;
    int aS = arow & 7;

    int grow = t & 63, gc0 = (t >> 6) * 2;
    const __half* gSrc = g_wg16 + ((size_t)e * NI + n0 + grow) * NH;
    const __half* uSrc = g_wu16 + ((size_t)e * NI + n0 + grow) * NH;
    uint32_t gDst = grow * 128;
    int gS = grow & 7;

    auto stage = [&](int kt, int st) {
        uint32_t base = sb + st * 32768;
#pragma unroll
        for (int j = 0; j < 4; j++) {
            int c = ac0 + j;
            cp16(base + aDst + ((c ^ aS) << 4), aSrc + kt * 64 + c * 8, tokA >= 0);
        }
#pragma unroll
        for (int j = 0; j < 2; j++) {
            int c = gc0 + j;
            cp16(base + 16384 + gDst + ((c ^ gS) << 4), gSrc + kt * 64 + c * 8, true);
            cp16(base + 24576 + gDst + ((c ^ gS) << 4), uSrc + kt * 64 + c * 8, true);
        }
        CP_COMMIT();
    };

    // ---- compute setup ----
    int wm = (wid & 3) * 32;
    int wn = (wid >> 2) * 32;
    int s7 = lane & 7;
    uint32_t aLdBase = sb + (wm + (lane & 7) + 8 * ((lane >> 3) & 1)) * 128;
    int aHi = lane >> 4;
    uint32_t bRow = (lane & 7) + 8 * (lane >> 4);
    int bHi = (lane >> 3) & 1;
    uint32_t gLdBase = sb + 16384 + (wn + bRow) * 128;
    uint32_t uLdBase = sb + 24576 + (wn + bRow) * 128;

    float accG[2][4][4] = {}, accU[2][4][4] = {};

    auto compute = [&](int st) {
        uint32_t so = st * 32768;
#pragma unroll
        for (int kf = 0; kf < 4; kf++) {
            uint32_t a[2][4], g[2][4], u[2][4];
            uint32_t aoff = (((2 * kf + aHi) ^ s7) << 4);
            uint32_t boff = (((2 * kf + bHi) ^ s7) << 4);
#pragma unroll
            for (int mf = 0; mf < 2; mf++) LDSM4(a[mf], aLdBase + so + mf * 2048 + aoff);
#pragma unroll
            for (int p = 0; p < 2; p++) {
                LDSM4(g[p], gLdBase + so + p * 2048 + boff);
                LDSM4(u[p], uLdBase + so + p * 2048 + boff);
            }
#pragma unroll
            for (int mf = 0; mf < 2; mf++)
#pragma unroll
                for (int nf = 0; nf < 4; nf++) {
                    int p = nf >> 1, o = (nf & 1) * 2;
                    mma16(accG[mf][nf], a[mf], g[p][o], g[p][o + 1]);
                    mma16(accU[mf][nf], a[mf], u[p][o], u[p][o + 1]);
                }
        }
    };

    const int NK = NH / 64;   // 16
    stage(0, 0);
    stage(1, 1);
    int st = 0;
    for (int kt = 0; kt < NK; kt++) {
        if (kt == NK - 1) { CP_WAIT0(); } else { CP_WAIT1(); }
        __syncthreads();
        compute(st);
        if (kt + 2 < NK) stage(kt + 2, (st + 2) % 3);
        st = (st + 1) % 3;
        // single barrier per iter (3-stage safety: stage writes (kt+2)%3,
        // whose previous compute finished before bar(kt)).
    }

    // ---- SwiGLU epilogue -> g_hmid16 ----
    int tg = lane >> 2, tc = lane & 3;
#pragma unroll
    for (int mf = 0; mf < 2; mf++) {
        int s0 = m0 + wm + mf * 16 + tg;
        int s1 = s0 + 8;
#pragma unroll
        for (int nf = 0; nf < 4; nf++) {
            int c = n0 + wn + nf * 8 + 2 * tc;
            const float* dG = accG[mf][nf];
            const float* dU = accU[mf][nf];
            if (s0 < cnt) {
                float h0 = (dG[0] / (1.f + __expf(-dG[0]))) * dU[0];
                float h1 = (dG[1] / (1.f + __expf(-dG[1]))) * dU[1];
                *(uint32_t*)(g_hmid16 + ((size_t)e * NT + s0) * NI + c) = packf16(h0, h1);
            }
            if (s1 < cnt) {
                float h2 = (dG[2] / (1.f + __expf(-dG[2]))) * dU[2];
                float h3 = (dG[3] / (1.f + __expf(-dG[3]))) * dU[3];
                *(uint32_t*)(g_hmid16 + ((size_t)e * NT + s1) * NI + c) = packf16(h2, h3);
            }
        }
    }
}

// ---------------- kernel 3: down GEMM + weighted combine (atomic) ----------------
#define DN_SMEM (3 * 32768)

__global__ void __launch_bounds__(256, 2) k_down(float* __restrict__ out) {
    int e   = blockIdx.z;
    int cnt = g_cnt[e];
    int m0  = blockIdx.y * 128;
    if (m0 >= cnt) return;
    int n0  = blockIdx.x * 128;   // over NH

    extern __shared__ unsigned char s_raw[];
    uint32_t sb = smem_u32(s_raw);

    int t = threadIdx.x, wid = t >> 5, lane = t & 31;

    // ---- staging setup ----
    int arow = t & 127, ac0 = (t >> 7) * 4;
    bool aValid = (m0 + arow < cnt);
    const __half* aSrc = g_hmid16 + ((size_t)e * NT + (aValid ? m0 + arow : 0)) * NI;
    uint32_t aDst = arow * 128;
    int aS = arow & 7;

    int brow = t & 127, bc0 = (t >> 7) * 4;
    const __half* bSrc = g_wd16 + ((size_t)e * NH + n0 + brow) * NI;
    uint32_t bDstO = 16384 + brow * 128;
    int bS = brow & 7;

    auto stage = [&](int kt, int st) {
        uint32_t base = sb + st * 32768;
#pragma unroll
        for (int j = 0; j < 4; j++) {
            int c = ac0 + j;
            cp16(base + aDst + ((c ^ aS) << 4), aSrc + kt * 64 + c * 8, aValid);
            int cb = bc0 + j;
            cp16(base + bDstO + ((cb ^ bS) << 4), bSrc + kt * 64 + cb * 8, true);
        }
        CP_COMMIT();
    };

    // ---- compute setup ----
    int wm = (wid & 3) * 32;
    int wn = (wid >> 2) * 64;
    int s7 = lane & 7;
    uint32_t aLdBase = sb + (wm + (lane & 7) + 8 * ((lane >> 3) & 1)) * 128;
    int aHi = lane >> 4;
    uint32_t bRow = (lane & 7) + 8 * (lane >> 4);
    int bHi = (lane >> 3) & 1;
    uint32_t bLdBase = sb + 16384 + (wn + bRow) * 128;

    float acc[2][8][4] = {};

    auto compute = [&](int st) {
        uint32_t so = st * 32768;
#pragma unroll
        for (int kf = 0; kf < 4; kf++) {
            uint32_t a[2][4], b[4][4];
            uint32_t aoff = (((2 * kf + aHi) ^ s7) << 4);
            uint32_t boff = (((2 * kf + bHi) ^ s7) << 4);
#pragma unroll
            for (int mf = 0; mf < 2; mf++) LDSM4(a[mf], aLdBase + so + mf * 2048 + aoff);
#pragma unroll
            for (int p = 0; p < 4; p++) LDSM4(b[p], bLdBase + so + p * 2048 + boff);
#pragma unroll
            for (int mf = 0; mf < 2; mf++)
#pragma unroll
                for (int nf = 0; nf < 8; nf++) {
                    int p = nf >> 1, o = (nf & 1) * 2;
                    mma16(acc[mf][nf], a[mf], b[p][o], b[p][o + 1]);
                }
        }
    };

    const int NK = NI / 64;   // 12
    stage(0, 0);
    stage(1, 1);
    int st = 0;
    for (int kt = 0; kt < NK; kt++) {
        if (kt == NK - 1) { CP_WAIT0(); } else { CP_WAIT1(); }
        __syncthreads();
        compute(st);
        if (kt + 2 < NK) stage(kt + 2, (st + 2) % 3);
        st = (st + 1) % 3;
        // single barrier per iter (3-stage safety argument, see k_gateup)
    }

    // ---- weighted combine epilogue (2 commutative fp32 adds per out element) ----
    int tg = lane >> 2, tc = lane & 3;
#pragma unroll
    for (int mf = 0; mf < 2; mf++) {
        int s0 = m0 + wm + mf * 16 + tg;
        int s1 = s0 + 8;
        int tok0 = -1, tok1 = -1; float w0 = 0.f, w1 = 0.f;
        if (s0 < cnt) { tok0 = g_tok[e][s0]; w0 = g_wt[e][s0]; }
        if (s1 < cnt) { tok1 = g_tok[e][s1]; w1 = g_wt[e][s1]; }
#pragma unroll
        for (int nf = 0; nf < 8; nf++) {
            int c = n0 + wn + nf * 8 + 2 * tc;
            const float* d = acc[mf][nf];
            if (tok0 >= 0) {
                atomicAdd(out + (size_t)tok0 * NH + c,     w0 * d[0]);
                atomicAdd(out + (size_t)tok0 * NH + c + 1, w0 * d[1]);
            }
            if (tok1 >= 0) {
                atomicAdd(out + (size_t)tok1 * NH + c,     w1 * d[2]);
                atomicAdd(out + (size_t)tok1 * NH + c + 1, w1 * d[3]);
            }
        }
    }
}

// ---------------- launch ----------------
extern "C" void kernel_launch(void* const* d_in, const int* in_sizes, int n_in,
                              void* d_out, int out_size) {
    (void)in_sizes; (void)n_in; (void)out_size;
    const float* x  = (const float*)d_in[0];
    const float* gw = (const float*)d_in[1];
    const float* gp = (const float*)d_in[2];
    const float* up = (const float*)d_in[3];
    const float* dp = (const float*)d_in[4];
    float* out = (float*)d_out;

    cudaFuncSetAttribute(k_gateup, cudaFuncAttributeMaxDynamicSharedMemorySize, GU_SMEM);
    cudaFuncSetAttribute(k_down,   cudaFuncAttributeMaxDynamicSharedMemorySize, DN_SMEM);

    void* cntAddr = nullptr;
    cudaGetSymbolAddress(&cntAddr, g_cnt);
    cudaMemsetAsync(cntAddr, 0, NE * sizeof(int));

    k_pre<<<PRE_RBLK + PRE_CBLK, 256, PRE_SMEM>>>(x, gw, gp, up);
    k_gateup<<<dim3(NI / 64, 16, NE + 1), 256, GU_SMEM>>>(dp, out);
    k_down<<<dim3(NH / 128, 16, NE), 256, DN_SMEM>>>(out);
}